// round 12
// baseline (speedup 1.0000x reference)
#include <cuda_runtime.h>

// Depth-5 path signature, B=256, d=10, L=128 (127 segments).
// Output row: [S1(10) | S2(100) | S3(1000) | S4(10000) | S5(100000)] = 111110 floats.
//
// Chen recurrence with rank-1 segment tensors (increment δ):
//   P3[abc] = S3/2 + δc*(S2/6 + δb*(S1/24 + δa/120))
//   Y3[abc] = S3   + δc*(S2/2 + δb*(S1/6  + δa/24))
//   X4[abcd] = S4[abcd] + δd*P3[abc];  S4 += Y3 ⊗ δ;  S5 += X4 ⊗ δ
//   S3 += δc*(S2 + δb*(S1/2 + δa/6));  S2 += δb*(S1 + δa/2);  S1 += δ
//
// R12: thread = (abc, e-half). Owns ALL 10 d as 5 packed d-pairs and 5 e-columns:
//   - X4/S4 packed over d: Xp[i] = ffma2((δ2i,δ2i+1), P3p, s4p[i]) — d-pairs via
//     LDS.128 straight from SMEM (kills R11's 10 SELs)
//   - S5 via broadcast pairs (δe,δe) from SMEM (kills R11's 5 pk(X,X) MOVs)
//   Same 46 fma per thread-iter for 50 S5 elements; alu 20 -> ~3, ~72 -> ~58 inst.
// Geometry: 224 thr (7 warps), launch_bounds(224,3) -> 97-reg cap (proven safe),
// live set ~91, 21 warps/SM, 9 CTAs per batch (0.8% idle threads).

#define NB 256
#define DCH 10
#define LEN 128
#define NSEG 127
#define THREADS 224
#define CTAS_PER_B 9
#define UNITS 2000          // (e-half, abc) units per batch
#define ROW 111110
#define APAD 12             // sdA row stride (floats): 48B rows, 16B-aligned
#define BPAD 12             // sdB row stride (ulls): 96B rows; halves at 0B / 48B

typedef unsigned long long ull;

__device__ __forceinline__ ull pk(float lo, float hi) {
    ull r;
    asm("mov.b64 %0, {%1, %2};" : "=l"(r) : "f"(lo), "f"(hi));
    return r;
}
__device__ __forceinline__ void upk(ull v, float& lo, float& hi) {
    asm("mov.b64 {%0, %1}, %2;" : "=f"(lo), "=f"(hi) : "l"(v));
}
__device__ __forceinline__ ull ffma2(ull a, ull b, ull c) {
    ull d;
    asm("fma.rn.f32x2 %0, %1, %2, %3;" : "=l"(d) : "l"(a), "l"(b), "l"(c));
    return d;
}

__global__ __launch_bounds__(THREADS, 3)
void sig_kernel(const float* __restrict__ path, float* __restrict__ out) {
    __shared__ __align__(16) float sdA[NSEG * APAD];  // [t][c] scalar deltas
    __shared__ __align__(16) ull   sdB[NSEG * BPAD];  // [t][eh*6 + l] = (δe,δe), e=5eh+l

    const int tid = threadIdx.x;
    const int b   = blockIdx.x / CTAS_PER_B;
    const int k   = blockIdx.x % CTAS_PER_B;

    // ---- segment increments into both SMEM layouts ----
    const float* pb = path + b * (DCH * LEN);
    for (int idx = tid; idx < NSEG * DCH; idx += THREADS) {
        int c = idx / NSEG, t = idx % NSEG;
        float d = pb[c * LEN + t + 1] - pb[c * LEN + t];
        sdA[t * APAD + c] = d;
        int eh = c / 5, l = c % 5;
        sdB[t * BPAD + eh * 6 + l] = pk(d, d);
    }
    __syncthreads();

    const int u = k * THREADS + tid;
    if (u >= UNITS) return;             // 16 idle threads in the last CTA per batch
    const int eh  = u / 1000;           // e-half: e = 5*eh + l
    const int abc = u % 1000;
    const int a   = abc / 100;
    const int hb  = (abc / 10) % 10;
    const int hc  = abc % 10;

    float s1 = 0.f, s2 = 0.f, s3 = 0.f;   // private S1[a], S2[ab], S3[abc]
    ull s4p[5];                            // [i] = (S4[abc,2i], S4[abc,2i+1])
    ull s5[5][5];                          // [i][l] = (S5[abc,2i,e], S5[abc,2i+1,e])
#pragma unroll
    for (int i = 0; i < 5; ++i) {
        s4p[i] = 0ull;
#pragma unroll
        for (int l = 0; l < 5; ++l) s5[i][l] = 0ull;
    }

    const float* dl = sdA;
    const ull*   bl = sdB + eh * 6;
    for (int t = 0; t < NSEG; ++t, dl += APAD, bl += BPAD) {
        // d-pairs via vector LDS (row 16B-aligned): (δ0,δ1)(δ2,δ3) | (δ4,δ5)(δ6,δ7) | (δ8,δ9)
        ulonglong2 q0 = *(const ulonglong2*)dl;
        ulonglong2 q1 = *(const ulonglong2*)(dl + 4);
        ull        q2 = *(const ull*)(dl + 8);
        // e-broadcast pairs for this half (base 0B or 48B, both 16B-aligned)
        ulonglong2 r0 = *(const ulonglong2*)bl;        // (δe0,δe0)(δe1,δe1)
        ulonglong2 r1 = *(const ulonglong2*)(bl + 2);  // (δe2,δe2)(δe3,δe3)
        ull        r2 = bl[4];                          // (δe4,δe4)
        float da = dl[a], db = dl[hb], dc = dl[hc];

        // Horner chains + private state update
        float P1 = fmaf(da, 1.f / 120.f, s1 * (1.f / 24.f));
        float P2 = fmaf(db, P1, s2 * (1.f / 6.f));
        float P3 = fmaf(dc, P2, s3 * 0.5f);
        float Q1 = fmaf(da, 1.f / 24.f, s1 * (1.f / 6.f));
        float Q2 = fmaf(db, Q1, s2 * 0.5f);
        float Y3 = fmaf(dc, Q2, s3);
        float Z1 = fmaf(da, 1.f / 6.f, s1 * 0.5f);
        float Z2 = fmaf(db, Z1, s2);
        s3 = fmaf(dc, Z2, s3);
        float W1 = fmaf(da, 0.5f, s1);
        s2 = fmaf(db, W1, s2);
        s1 += da;

        ull P3p = pk(P3, P3), Y3p = pk(Y3, Y3);

        // packed X4 / S4 over d-pairs
        ull Xp[5];
        Xp[0] = ffma2(q0.x, P3p, s4p[0]);  s4p[0] = ffma2(q0.x, Y3p, s4p[0]);
        Xp[1] = ffma2(q0.y, P3p, s4p[1]);  s4p[1] = ffma2(q0.y, Y3p, s4p[1]);
        Xp[2] = ffma2(q1.x, P3p, s4p[2]);  s4p[2] = ffma2(q1.x, Y3p, s4p[2]);
        Xp[3] = ffma2(q1.y, P3p, s4p[3]);  s4p[3] = ffma2(q1.y, Y3p, s4p[3]);
        Xp[4] = ffma2(q2,   P3p, s4p[4]);  s4p[4] = ffma2(q2,   Y3p, s4p[4]);

        // S5: 25 independent packed FMAs, zero pack/SEL overhead
#pragma unroll
        for (int i = 0; i < 5; ++i) {
            s5[i][0] = ffma2(Xp[i], r0.x, s5[i][0]);
            s5[i][1] = ffma2(Xp[i], r0.y, s5[i][1]);
            s5[i][2] = ffma2(Xp[i], r1.x, s5[i][2]);
            s5[i][3] = ffma2(Xp[i], r1.y, s5[i][3]);
            s5[i][4] = ffma2(Xp[i], r2,   s5[i][4]);
        }
    }

    // ---- epilogue ----
    float* orow = out + (size_t)b * ROW;
    if (eh == 0) {
        if (hb == 0 && hc == 0) orow[a] = s1;
        if (hc == 0) orow[10 + a * 10 + hb] = s2;
        orow[110 + abc] = s3;
        ull* o4 = (ull*)(orow + 1110 + abc * 10);  // even float offset -> STG.64
#pragma unroll
        for (int i = 0; i < 5; ++i) o4[i] = s4p[i];
    }
    // S5: s5[i][l] = rows d=2i, 2i+1 at column e=5*eh+l of this abc's 100-block
    float* o5 = orow + 11110 + abc * 100 + 5 * eh;
#pragma unroll
    for (int i = 0; i < 5; ++i) {
#pragma unroll
        for (int l = 0; l < 5; ++l) {
            float lo, hi;
            upk(s5[i][l], lo, hi);
            o5[(2 * i) * 10 + l]     = lo;
            o5[(2 * i + 1) * 10 + l] = hi;
        }
    }
}

extern "C" void kernel_launch(void* const* d_in, const int* in_sizes, int n_in,
                              void* d_out, int out_size) {
    const float* path = (const float*)d_in[0];  // (256, 10, 128) fp32
    float* out = (float*)d_out;                 // (256, 111110) fp32
    sig_kernel<<<NB * CTAS_PER_B, THREADS>>>(path, out);
}

// round 13
// speedup vs baseline: 2.0158x; 2.0158x over previous
#include <cuda_runtime.h>

// Depth-5 path signature, B=256, d=10, L=128 (127 segments).
// Output row: [S1(10) | S2(100) | S3(1000) | S4(10000) | S5(100000)] = 111110 floats.
//
// Chen recurrence with rank-1 segment tensors (increment δ):
//   P3[abc] = S3/2 + δc*(S2/6 + δb*(S1/24 + δa/120))
//   Y3[abc] = S3   + δc*(S2/2 + δb*(S1/6  + δa/24))
//   X4[abcd] = S4[abcd] + δd*P3[abc];  S4 += Y3 ⊗ δ;  S5 += X4 ⊗ δ
//   S3 += δc*(S2 + δb*(S1/2 + δa/6));  S2 += δb*(S1 + δa/2);  S1 += δ
//
// R13 = R11 (235.6us champion: 256thr x3 CTAs, 80 regs, 24 warps/SM, zero
// barriers) with reg-neutral instruction trims:
//   1. e-pairs loaded as ulonglong2 straight from sdA rows (-5 pack MOVs)
//   2. dloc via half-grouped layout sdH = [evens | odds@24B]: 2xLDS.64+LDS.32
//      replaces 5 SELs and yields dloc PAIRS for free
//   3. X4/S4 packed over i-pairs with packed s4 state: 10 scalar fma -> 6 issues
// Per-iter issues ~77 -> ~68; register peak unchanged (X2 one-at-a-time).

#define NB 256
#define DCH 10
#define LEN 128
#define NSEG 127
#define THREADS 256
#define CTAS_PER_B 8
#define UNITS 2000
#define ROW 111110
#define APAD 12   // row stride (floats) for both layouts: 48B, 16B-aligned

typedef unsigned long long ull;

__device__ __forceinline__ ull pk(float lo, float hi) {
    ull r;
    asm("mov.b64 %0, {%1, %2};" : "=l"(r) : "f"(lo), "f"(hi));
    return r;
}
__device__ __forceinline__ void upk(ull v, float& lo, float& hi) {
    asm("mov.b64 {%0, %1}, %2;" : "=f"(lo), "=f"(hi) : "l"(v));
}
__device__ __forceinline__ ull ffma2(ull a, ull b, ull c) {
    ull d;
    asm("fma.rn.f32x2 %0, %1, %2, %3;" : "=l"(d) : "l"(a), "l"(b), "l"(c));
    return d;
}

__global__ __launch_bounds__(THREADS, 3)
void sig_kernel(const float* __restrict__ path, float* __restrict__ out) {
    __shared__ __align__(16) float sdA[NSEG * APAD];  // [t][c]: δ0..δ9
    __shared__ __align__(16) float sdH[NSEG * APAD];  // [t]: δ0,δ2,δ4,δ6,δ8,_,δ1,δ3,δ5,δ7,δ9,_

    const int tid = threadIdx.x;
    const int b   = blockIdx.x / CTAS_PER_B;
    const int k   = blockIdx.x % CTAS_PER_B;

    // ---- segment increments into both layouts ----
    const float* pb = path + b * (DCH * LEN);
    for (int idx = tid; idx < NSEG * DCH; idx += THREADS) {
        int c = idx / NSEG, t = idx % NSEG;
        float d = pb[c * LEN + t + 1] - pb[c * LEN + t];
        sdA[t * APAD + c] = d;
        sdH[t * APAD + (c & 1) * 6 + (c >> 1)] = d;
    }
    __syncthreads();

    const int u = k * THREADS + tid;
    if (u >= UNITS) return;
    const int half = u / 1000;          // d = 2*i + half
    const int abc  = u % 1000;
    const int a    = abc / 100;
    const int hb   = (abc / 10) % 10;
    const int hc   = abc % 10;

    float s1 = 0.f, s2 = 0.f, s3 = 0.f;   // private S1[a], S2[ab], S3[abc]
    ull   s4a = 0ull, s4b = 0ull;          // (S4[d=half],S4[d=2+half]) , (4+half,6+half)
    float s4c = 0.f;                       // S4[d=8+half]
    ull   s5[5][5];                        // [i][e-pair p]
#pragma unroll
    for (int i = 0; i < 5; ++i)
#pragma unroll
        for (int p = 0; p < 5; ++p) s5[i][p] = 0ull;

    const float* dl = sdA;
    const float* hl = sdH + half * 6;
    for (int t = 0; t < NSEG; ++t, dl += APAD, hl += APAD) {
        // e-pairs directly from the row (16B-aligned): (δ0,δ1)(δ2,δ3) | (δ4,δ5)(δ6,δ7) | (δ8,δ9)
        ulonglong2 e01 = *(const ulonglong2*)dl;
        ulonglong2 e23 = *(const ulonglong2*)(dl + 4);
        ull        e4  = *(const ull*)(dl + 8);
        // own-half d-values as pairs (8B-aligned: half*24B)
        ull   dp01  = *(const ull*)hl;        // (δ_half, δ_{2+half})
        ull   dp23  = *(const ull*)(hl + 2);  // (δ_{4+half}, δ_{6+half})
        float dloc4 = hl[4];                  // δ_{8+half}
        float da = dl[a], db = dl[hb], dc = dl[hc];

        // Horner chains + private state update (scalar, proven 80-reg body)
        float P1 = fmaf(da, 1.f / 120.f, s1 * (1.f / 24.f));
        float P2 = fmaf(db, P1, s2 * (1.f / 6.f));
        float P3 = fmaf(dc, P2, s3 * 0.5f);
        float Q1 = fmaf(da, 1.f / 24.f, s1 * (1.f / 6.f));
        float Q2 = fmaf(db, Q1, s2 * 0.5f);
        float Y3 = fmaf(dc, Q2, s3);
        float Z1 = fmaf(da, 1.f / 6.f, s1 * 0.5f);
        float Z2 = fmaf(db, Z1, s2);
        s3 = fmaf(dc, Z2, s3);
        float W1 = fmaf(da, 0.5f, s1);
        s2 = fmaf(db, W1, s2);
        s1 += da;

        // packed X4 / S4 over i-pairs
        ull P3p = pk(P3, P3), Y3p = pk(Y3, Y3);
        ull Xa = ffma2(dp01, P3p, s4a);  s4a = ffma2(dp01, Y3p, s4a);
        ull Xb = ffma2(dp23, P3p, s4b);  s4b = ffma2(dp23, Y3p, s4b);
        float Xc = fmaf(dloc4, P3, s4c); s4c = fmaf(dloc4, Y3, s4c);

        float xs0, xs1, xs2, xs3;
        upk(Xa, xs0, xs1);
        upk(Xb, xs2, xs3);
        float xs[5] = {xs0, xs1, xs2, xs3, Xc};
        ull ep[5] = {e01.x, e01.y, e23.x, e23.y, e4};

#pragma unroll
        for (int i = 0; i < 5; ++i) {
            ull X2 = pk(xs[i], xs[i]);
#pragma unroll
            for (int p = 0; p < 5; ++p)
                s5[i][p] = ffma2(X2, ep[p], s5[i][p]);   // S5[abc,2i+half,·] += X4*δe
        }
    }

    // ---- epilogue ----
    float* orow = out + (size_t)b * ROW;
    if (half == 0) {
        if (hb == 0 && hc == 0) orow[a] = s1;
        if (hc == 0) orow[10 + a * 10 + hb] = s2;
        orow[110 + abc] = s3;
    }
    // S4 scalars: lanes of s4a/s4b + s4c, d = 2i+half
    {
        float v0, v1, v2, v3;
        upk(s4a, v0, v1);
        upk(s4b, v2, v3);
        float* o4 = orow + 1110 + abc * 10 + half;
        o4[0] = v0; o4[2] = v1; o4[4] = v2; o4[6] = v3; o4[8] = s4c;
    }
    ull* o5 = (ull*)(orow + 11110);   // 8B-aligned
#pragma unroll
    for (int i = 0; i < 5; ++i) {
        int abcd = abc * 10 + 2 * i + half;
#pragma unroll
        for (int p = 0; p < 5; ++p) o5[abcd * 5 + p] = s5[i][p];
    }
}

extern "C" void kernel_launch(void* const* d_in, const int* in_sizes, int n_in,
                              void* d_out, int out_size) {
    const float* path = (const float*)d_in[0];  // (256, 10, 128) fp32
    float* out = (float*)d_out;                 // (256, 111110) fp32
    sig_kernel<<<NB * CTAS_PER_B, THREADS>>>(path, out);
}

// round 15
// speedup vs baseline: 2.1339x; 1.0586x over previous
#include <cuda_runtime.h>

// Depth-5 path signature, B=256, d=10, L=128 (127 segments).
// Output row: [S1(10) | S2(100) | S3(1000) | S4(10000) | S5(100000)] = 111110 floats.
//
// Chen recurrence with rank-1 segment tensors (increment δ):
//   P3[abc] = S3/2 + δc*(S2/6 + δb*(S1/24 + δa/120))
//   Y3[abc] = S3   + δc*(S2/2 + δb*(S1/6  + δa/24))
//   X4[abcd] = S4[abcd] + δd*P3[abc];  S4 += Y3 ⊗ δ;  S5 += X4 ⊗ δ
//   S3 += δc*(S2 + δb*(S1/2 + δa/6));  S2 += δb*(S1 + δa/2);  S1 += δ
//
// R14 = R13 body, UNROLL x2 at launch_bounds(256,2):
//   reg cap 128 (wide margin over ~105 live set, no spill either direction),
//   16 warps/SM; per-warp ILP doubles — the 25-ffma2 S5(t) block overlaps the
//   LDS + 8-deep Horner head of iteration t+1 (R11/R13 were stall-bound at
//   issue=54% with warps in lockstep at each iteration head).
// NSEG padded to 128 with a zero row: δ=0 provably leaves all state unchanged.

#define NB 256
#define DCH 10
#define LEN 128
#define NSEG 127
#define PADSEG 128
#define THREADS 256
#define CTAS_PER_B 8
#define UNITS 2000
#define ROW 111110
#define APAD 12   // row stride (floats): 48B, 16B-aligned

typedef unsigned long long ull;

__device__ __forceinline__ ull pk(float lo, float hi) {
    ull r;
    asm("mov.b64 %0, {%1, %2};" : "=l"(r) : "f"(lo), "f"(hi));
    return r;
}
__device__ __forceinline__ void upk(ull v, float& lo, float& hi) {
    asm("mov.b64 {%0, %1}, %2;" : "=f"(lo), "=f"(hi) : "l"(v));
}
__device__ __forceinline__ ull ffma2(ull a, ull b, ull c) {
    ull d;
    asm("fma.rn.f32x2 %0, %1, %2, %3;" : "=l"(d) : "l"(a), "l"(b), "l"(c));
    return d;
}

__global__ __launch_bounds__(THREADS, 2)
void sig_kernel(const float* __restrict__ path, float* __restrict__ out) {
    __shared__ __align__(16) float sdA[PADSEG * APAD];  // [t][c]: δ0..δ9
    __shared__ __align__(16) float sdH[PADSEG * APAD];  // [t]: evens | odds@24B

    const int tid = threadIdx.x;
    const int b   = blockIdx.x / CTAS_PER_B;
    const int k   = blockIdx.x % CTAS_PER_B;

    // ---- segment increments into both layouts (+ zero pad row t=127) ----
    const float* pb = path + b * (DCH * LEN);
    for (int idx = tid; idx < NSEG * DCH; idx += THREADS) {
        int c = idx / NSEG, t = idx % NSEG;
        float d = pb[c * LEN + t + 1] - pb[c * LEN + t];
        sdA[t * APAD + c] = d;
        sdH[t * APAD + (c & 1) * 6 + (c >> 1)] = d;
    }
    if (tid < APAD) {
        sdA[NSEG * APAD + tid] = 0.f;
        sdH[NSEG * APAD + tid] = 0.f;
    }
    __syncthreads();

    const int u = k * THREADS + tid;
    if (u >= UNITS) return;
    const int half = u / 1000;          // d = 2*i + half
    const int abc  = u % 1000;
    const int a    = abc / 100;
    const int hb   = (abc / 10) % 10;
    const int hc   = abc % 10;

    float s1 = 0.f, s2 = 0.f, s3 = 0.f;
    ull   s4a = 0ull, s4b = 0ull;       // (S4[half],S4[2+half]) , (4+half,6+half)
    float s4c = 0.f;                    // S4[8+half]
    ull   s5[5][5];
#pragma unroll
    for (int i = 0; i < 5; ++i)
#pragma unroll
        for (int p = 0; p < 5; ++p) s5[i][p] = 0ull;

    const float* dl = sdA;
    const float* hl = sdH + half * 6;
    for (int t = 0; t < PADSEG; t += 2) {
#pragma unroll
        for (int w = 0; w < 2; ++w) {
            const float* dlw = dl + w * APAD;
            const float* hlw = hl + w * APAD;
            // e-pairs straight from the row (16B-aligned)
            ulonglong2 e01 = *(const ulonglong2*)dlw;
            ulonglong2 e23 = *(const ulonglong2*)(dlw + 4);
            ull        e4  = *(const ull*)(dlw + 8);
            // own-half d-values as pairs (8B-aligned)
            ull   dp01  = *(const ull*)hlw;
            ull   dp23  = *(const ull*)(hlw + 2);
            float dloc4 = hlw[4];
            float da = dlw[a], db = dlw[hb], dc = dlw[hc];

            // Horner chains + private state update
            float P1 = fmaf(da, 1.f / 120.f, s1 * (1.f / 24.f));
            float P2 = fmaf(db, P1, s2 * (1.f / 6.f));
            float P3 = fmaf(dc, P2, s3 * 0.5f);
            float Q1 = fmaf(da, 1.f / 24.f, s1 * (1.f / 6.f));
            float Q2 = fmaf(db, Q1, s2 * 0.5f);
            float Y3 = fmaf(dc, Q2, s3);
            float Z1 = fmaf(da, 1.f / 6.f, s1 * 0.5f);
            float Z2 = fmaf(db, Z1, s2);
            s3 = fmaf(dc, Z2, s3);
            float W1 = fmaf(da, 0.5f, s1);
            s2 = fmaf(db, W1, s2);
            s1 += da;

            // packed X4 / S4 over i-pairs
            ull P3p = pk(P3, P3), Y3p = pk(Y3, Y3);
            ull Xa = ffma2(dp01, P3p, s4a);  s4a = ffma2(dp01, Y3p, s4a);
            ull Xb = ffma2(dp23, P3p, s4b);  s4b = ffma2(dp23, Y3p, s4b);
            float Xc = fmaf(dloc4, P3, s4c); s4c = fmaf(dloc4, Y3, s4c);

            float xs0, xs1, xs2, xs3;
            upk(Xa, xs0, xs1);
            upk(Xb, xs2, xs3);
            float xs[5] = {xs0, xs1, xs2, xs3, Xc};
            ull ep[5] = {e01.x, e01.y, e23.x, e23.y, e4};

#pragma unroll
            for (int i = 0; i < 5; ++i) {
                ull X2 = pk(xs[i], xs[i]);
#pragma unroll
                for (int p = 0; p < 5; ++p)
                    s5[i][p] = ffma2(X2, ep[p], s5[i][p]);
            }
        }
        dl += 2 * APAD;
        hl += 2 * APAD;
    }

    // ---- epilogue ----
    float* orow = out + (size_t)b * ROW;
    if (half == 0) {
        if (hb == 0 && hc == 0) orow[a] = s1;
        if (hc == 0) orow[10 + a * 10 + hb] = s2;
        orow[110 + abc] = s3;
    }
    {
        float v0, v1, v2, v3;
        upk(s4a, v0, v1);
        upk(s4b, v2, v3);
        float* o4 = orow + 1110 + abc * 10 + half;
        o4[0] = v0; o4[2] = v1; o4[4] = v2; o4[6] = v3; o4[8] = s4c;
    }
    ull* o5 = (ull*)(orow + 11110);   // 8B-aligned
#pragma unroll
    for (int i = 0; i < 5; ++i) {
        int abcd = abc * 10 + 2 * i + half;
#pragma unroll
        for (int p = 0; p < 5; ++p) o5[abcd * 5 + p] = s5[i][p];
    }
}

extern "C" void kernel_launch(void* const* d_in, const int* in_sizes, int n_in,
                              void* d_out, int out_size) {
    const float* path = (const float*)d_in[0];  // (256, 10, 128) fp32
    float* out = (float*)d_out;                 // (256, 111110) fp32
    sig_kernel<<<NB * CTAS_PER_B, THREADS>>>(path, out);
}